// round 10
// baseline (speedup 1.0000x reference)
#include <cuda_runtime.h>
#include <cstdint>
#include <math_constants.h>

#define BATCH   16384
#define S       2048
#define G       256
#define NT      256
#define EPT     (S / NT)   // 8
#define LISTCAP 32
#define RANKW   1793u
#define RANKL   256u
#define TLO     1.0f       // tail threshold for predicated histogram

// ---- order-preserving float<->uint transforms (fallback path only) ----
__device__ __forceinline__ uint32_t f2u(float f) {
    uint32_t b = __float_as_uint(f);
    return b ^ ((b & 0x80000000u) ? 0xFFFFFFFFu : 0x80000000u);
}
__device__ __forceinline__ float u2f(uint32_t u) {
    uint32_t b = (u & 0x80000000u) ? (u ^ 0x80000000u) : ~u;
    return __uint_as_float(b);
}

// tail bin: x in (1.0, inf) -> bin over [1.0,1.5), 1/512 wide, bin 255 = catch-all
__device__ __forceinline__ int tailbin(float x) {
    return min(__float2int_rd(fmaf(x, 512.0f, -512.0f)), 255);
}

// ---- block exclusive scan (u32), 256 threads ----
__device__ __forceinline__ uint32_t block_exscan_u32(uint32_t v, uint32_t* st) {
    const uint32_t full = 0xffffffffu;
    int lane = threadIdx.x & 31, w = threadIdx.x >> 5;
    uint32_t inc = v;
#pragma unroll
    for (int o = 1; o < 32; o <<= 1) {
        uint32_t t = __shfl_up_sync(full, inc, o);
        if (lane >= o) inc += t;
    }
    if (lane == 31) st[w] = inc;
    __syncthreads();
    if (threadIdx.x < 32) {
        uint32_t t = (lane < 8) ? st[lane] : 0u;
        uint32_t it = t;
#pragma unroll
        for (int o = 1; o < 8; o <<= 1) {
            uint32_t x = __shfl_up_sync(full, it, o);
            if (lane >= o) it += x;
        }
        if (lane < 8) st[lane] = it - t;
    }
    __syncthreads();
    uint32_t r = (inc - v) + st[w];
    __syncthreads();
    return r;
}

// ---- block exclusive scan (packed u64, two independent u32 halves) ----
__device__ __forceinline__ unsigned long long block_exscan_u64(unsigned long long v,
                                                               unsigned long long* st) {
    const uint32_t full = 0xffffffffu;
    int lane = threadIdx.x & 31, w = threadIdx.x >> 5;
    unsigned long long inc = v;
#pragma unroll
    for (int o = 1; o < 32; o <<= 1) {
        unsigned long long t = __shfl_up_sync(full, inc, o);
        if (lane >= o) inc += t;
    }
    if (lane == 31) st[w] = inc;
    __syncthreads();
    if (threadIdx.x < 32) {
        unsigned long long t = (lane < 8) ? st[lane] : 0ull;
        unsigned long long it = t;
#pragma unroll
        for (int o = 1; o < 8; o <<= 1) {
            unsigned long long x = __shfl_up_sync(full, it, o);
            if (lane >= o) it += x;
        }
        if (lane < 8) st[lane] = it - t;
    }
    __syncthreads();
    unsigned long long r = (inc - v) + st[w];
    __syncthreads();
    return r;
}

// ---- rare fallback: exact key radix select (11/11/10 bits), one rank ----
__device__ uint32_t radix_one_f(const float* fr, uint32_t rank,
                                uint32_t* hist, uint32_t* st, uint32_t* pub) {
    const int tid = threadIdx.x;
    uint32_t pfx = 0, r = rank;
#pragma unroll
    for (int rnd = 0; rnd < 3; rnd++) {
        reinterpret_cast<uint4*>(hist)[tid] = make_uint4(0, 0, 0, 0);
        reinterpret_cast<uint4*>(hist)[NT + tid] = make_uint4(0, 0, 0, 0);
        __syncthreads();
#pragma unroll
        for (int k = 0; k < EPT; k++) {
            uint32_t u = f2u(fr[k]);
            bool ok; uint32_t bin;
            if (rnd == 0)      { ok = true;                bin = u >> 21; }
            else if (rnd == 1) { ok = (u >> 21) == pfx;    bin = (u >> 10) & 0x7FFu; }
            else               { ok = (u >> 10) == pfx;    bin = u & 0x3FFu; }
            if (ok) atomicAdd(&hist[bin], 1u);
        }
        __syncthreads();
        const int nb = (rnd == 2) ? 4 : 8;
        uint32_t c[8], sum = 0;
#pragma unroll
        for (int k = 0; k < 8; k++) {
            c[k] = (k < nb) ? hist[tid * nb + k] : 0u;
            sum += c[k];
        }
        uint32_t exc = block_exscan_u32(sum, st);
        if (exc < r && r <= exc + sum) {
            uint32_t run = exc;
#pragma unroll
            for (int k = 0; k < 8; k++) {
                if (k < nb && r > run && r <= run + c[k]) {
                    pub[18] = tid * nb + k; pub[19] = r - run;
                }
                run += c[k];
            }
        }
        __syncthreads();
        uint32_t bin = pub[18]; r = pub[19];
        __syncthreads();
        pfx = (rnd == 2) ? ((pfx << 10) | bin) : ((pfx << 11) | bin);
    }
    return pfx;
}

__global__ __launch_bounds__(NT, 6)
void portfolio_kernel(const float* __restrict__ scores,
                      const float* __restrict__ short_ratio,
                      float* __restrict__ out) {
    const int row = blockIdx.x;
    const int tid = threadIdx.x;
    const int lane = tid & 31;
    const int wid = tid >> 5;
    const uint32_t full = 0xffffffffu;

    __shared__ __align__(16) uint32_t hist[2048];   // fast: hA=[0,256) hB=[256,512); fallback: all
    __shared__ uint32_t st32[8];
    __shared__ unsigned long long st64[8];
    __shared__ float wmaxs[8], wmins[8];
    __shared__ uint32_t pub[20];
    __shared__ uint32_t pub2[8];
    __shared__ uint32_t cnt2[2];
    __shared__ float listW[LISTCAP], listL[LISTCAP];
    __shared__ float sredf[16];
    __shared__ unsigned long long sredu[8];

    uint32_t* const hA = hist;
    uint32_t* const hB = hist + 256;

    // ---- load row, local max/min, clear tail histograms ----
    const float4* rowp = reinterpret_cast<const float4*>(scores + (size_t)row * S);
    float fr[8];
    float lmax = -CUDART_INF_F, lmin = CUDART_INF_F;
#pragma unroll
    for (int k = 0; k < 2; k++) {
        float4 v = rowp[tid + k * NT];
        fr[k * 4 + 0] = v.x; fr[k * 4 + 1] = v.y; fr[k * 4 + 2] = v.z; fr[k * 4 + 3] = v.w;
        lmax = fmaxf(lmax, fmaxf(fmaxf(v.x, v.y), fmaxf(v.z, v.w)));
        lmin = fminf(lmin, fminf(fminf(v.x, v.y), fminf(v.z, v.w)));
    }
    hA[tid] = 0;
    hB[tid] = 0;
    if (tid < 2) cnt2[tid] = 0;
#pragma unroll
    for (int o = 16; o; o >>= 1) {
        lmax = fmaxf(lmax, __shfl_xor_sync(full, lmax, o));
        lmin = fminf(lmin, __shfl_xor_sync(full, lmin, o));
    }
    if (lane == 0) { wmaxs[wid] = lmax; wmins[wid] = lmin; }
    __syncthreads();

    // ---- predicated tail histograms (~16% of elements per side) ----
#pragma unroll
    for (int k = 0; k < EPT; k++) {
        float s = fr[k];
        if (s > TLO)  atomicAdd(&hA[tailbin(s)], 1u);
        if (s < -TLO) atomicAdd(&hB[tailbin(-s)], 1u);
    }
    if (tid < 32) {   // warp 0 finalizes min/max meanwhile
        float a = (lane < 8) ? wmaxs[lane] : -CUDART_INF_F;
        float b = (lane < 8) ? wmins[lane] : CUDART_INF_F;
#pragma unroll
        for (int o = 4; o; o >>= 1) {
            a = fmaxf(a, __shfl_xor_sync(full, a, o));
            b = fminf(b, __shfl_xor_sync(full, b, o));
        }
        if (lane == 0) { pub[6] = __float_as_uint(a); pub[7] = __float_as_uint(b); }
    }
    __syncthreads();
    const float maxF = __uint_as_float(pub[6]);
    const float minF = __uint_as_float(pub[7]);

    // ---- packed scan over both tail histograms; totals published by last thread ----
    const uint32_t sa = hA[tid], sb = hB[tid];
    unsigned long long e =
        block_exscan_u64((unsigned long long)sa | ((unsigned long long)sb << 32), st64);
    const uint32_t ea = (uint32_t)e, eb = (uint32_t)(e >> 32);
    if (tid == NT - 1) { pub[0] = ea + sa; pub[1] = eb + sb; }
    __syncthreads();
    const uint32_t nGT = pub[0], nLT = pub[1];
    const bool flagOK = (nGT >= (uint32_t)G) && (nLT >= (uint32_t)G);

    if (flagOK) {
        const uint32_t rWt = nGT - (G - 1);   // ascending rank within hA
        const uint32_t rLt = nLT - (G - 1);   // ascending rank within hB (t = -s domain)
        if (ea < rWt && rWt <= ea + sa) {
            pub[9] = (uint32_t)tid; pub[10] = ea; pub[11] = sa; pub[12] = rWt - ea;
        }
        if (eb < rLt && rLt <= eb + sb) {
            pub[13] = (uint32_t)tid; pub[14] = eb; pub[15] = sb; pub[16] = rLt - eb;
        }
    }
    __syncthreads();
    const int binW = (int)pub[9];  const uint32_t FPw = pub[10], FCw = pub[11], rWf = pub[12];
    const int binL = (int)pub[13]; const uint32_t FPl = pub[14], FCl = pub[15], rLf = pub[16];
    const bool fastsel = flagOK && (FCw <= LISTCAP) && (FCl <= LISTCAP);

    float swv, slv, sW, sL;
    int nWgt, nWeq, nLlt, nLeq;

    if (fastsel) {
        // ---- fused capture + tail exp-sums (only tail elements touched) ----
        float sWc = 0.0f, sLc = 0.0f;
#pragma unroll
        for (int k = 0; k < EPT; k++) {
            float s = fr[k];
            if (s > TLO) {
                int b = tailbin(s);
                if (b > binW) sWc += __expf(s - maxF);
                else if (b == binW) {
                    uint32_t i = atomicAdd(&cnt2[0], 1u);
                    if (i < LISTCAP) listW[i] = s;
                }
            }
            if (s < -TLO) {
                float t = -s;
                int b = tailbin(t);
                if (b > binL) sLc += __expf(minF - s);
                else if (b == binL) {
                    uint32_t i = atomicAdd(&cnt2[1], 1u);
                    if (i < LISTCAP) listL[i] = t;   // store t = -s (ascending sort)
                }
            }
        }
#pragma unroll
        for (int o = 16; o; o >>= 1) {
            sWc += __shfl_xor_sync(full, sWc, o);
            sLc += __shfl_xor_sync(full, sLc, o);
        }
        if (lane == 0) { sredf[wid] = sWc; sredf[8 + wid] = sLc; }
        __syncthreads();

        // ---- warps 0/1: sort candidates + ballots; warp 2: finalize tail sums ----
        if (wid < 2) {
            const uint32_t n = (wid == 0) ? FCw : FCl;
            float v = ((uint32_t)lane < n) ? (wid == 0 ? listW[lane] : listL[lane])
                                           : CUDART_INF_F;
#pragma unroll
            for (int k = 2; k <= 32; k <<= 1) {
#pragma unroll
                for (int j = k >> 1; j > 0; j >>= 1) {
                    float o = __shfl_xor_sync(full, v, j);
                    bool up = ((lane & k) == 0);
                    bool lower = ((lane & j) == 0);
                    float mn = fminf(v, o), mx = fmaxf(v, o);
                    v = (lower == up) ? mn : mx;
                }
            }
            uint32_t rank = (wid == 0) ? rWf : rLf;   // 1-based ascending
            float sel = __shfl_sync(full, v, (int)(rank - 1));
            bool valid = ((uint32_t)lane < n);
            uint32_t mgt = __ballot_sync(full, valid && v > sel);
            uint32_t meq = __ballot_sync(full, valid && v == sel);
            float cs = (valid && v > sel)
                         ? ((wid == 0) ? __expf(v - maxF) : __expf(minF + v))
                         : 0.0f;
#pragma unroll
            for (int o = 16; o; o >>= 1) cs += __shfl_xor_sync(full, cs, o);
            if (lane == 0) {
                int base = (wid == 0) ? 0 : 4;
                pub2[base + 0] = __float_as_uint(sel);
                pub2[base + 1] = __popc(mgt);
                pub2[base + 2] = __popc(meq);
                pub2[base + 3] = __float_as_uint(cs);
            }
        } else if (wid == 2) {
            float a = (lane < 8) ? sredf[lane] : 0.0f;
            float b = (lane < 8) ? sredf[8 + lane] : 0.0f;
#pragma unroll
            for (int o = 4; o; o >>= 1) {
                a += __shfl_xor_sync(full, a, o);
                b += __shfl_xor_sync(full, b, o);
            }
            if (lane == 0) { sredf[0] = a; sredf[8] = b; }
        }
        __syncthreads();

        swv  = __uint_as_float(pub2[0]);
        nWgt = (int)(nGT - FPw - FCw) + (int)pub2[1];
        nWeq = (int)pub2[2];
        sW   = sredf[0] + __uint_as_float(pub2[3]);
        slv  = -__uint_as_float(pub2[4]);               // back to s-domain
        nLlt = (int)(nLT - FPl - FCl) + (int)pub2[5];
        nLeq = (int)pub2[6];
        sL   = sredf[8] + __uint_as_float(pub2[7]);
    } else {
        // ---- RARE fallback: exact full-key radix select + full count pass ----
        uint32_t kW = radix_one_f(fr, RANKW, hist, st32, pub);
        uint32_t kL = radix_one_f(fr, RANKL, hist, st32, pub);
        swv = u2f(kW);
        slv = u2f(kL);
        unsigned long long packed = 0ull;
        float a2 = 0.0f, b2 = 0.0f;
#pragma unroll
        for (int k = 0; k < EPT; k++) {
            float s = fr[k];
            bool gtW = (s > swv), eqW = (s == swv), ltL = (s < slv), eqL = (s == slv);
            float ex = __expf(gtW ? (s - maxF) : (minF - s));
            a2 += gtW ? ex : 0.0f;
            b2 += ltL ? ex : 0.0f;
            packed += (unsigned long long)gtW
                    + ((unsigned long long)eqW << 16)
                    + ((unsigned long long)ltL << 32)
                    + ((unsigned long long)eqL << 48);
        }
#pragma unroll
        for (int o = 16; o; o >>= 1) {
            packed += __shfl_xor_sync(full, packed, o);
            a2 += __shfl_xor_sync(full, a2, o);
            b2 += __shfl_xor_sync(full, b2, o);
        }
        if (lane == 0) { sredu[wid] = packed; sredf[wid] = a2; sredf[8 + wid] = b2; }
        __syncthreads();
        if (tid < 32) {
            unsigned long long c = (lane < 8) ? sredu[lane] : 0ull;
            float a = (lane < 8) ? sredf[lane] : 0.0f;
            float b = (lane < 8) ? sredf[8 + lane] : 0.0f;
#pragma unroll
            for (int o = 4; o; o >>= 1) {
                c += __shfl_xor_sync(full, c, o);
                a += __shfl_xor_sync(full, a, o);
                b += __shfl_xor_sync(full, b, o);
            }
            if (lane == 0) { sredu[0] = c; sredf[0] = a; sredf[8] = b; }
        }
        __syncthreads();
        packed = sredu[0];
        sW = sredf[0];
        sL = sredf[8];
        nWgt = (int)(packed & 0xFFFFu);
        nWeq = (int)((packed >> 16) & 0xFFFFu);
        nLlt = (int)((packed >> 32) & 0xFFFFu);
        nLeq = (int)((packed >> 48) & 0xFFFFu);
    }

    const int eWc = G - nWgt;
    const int eLc = G - nLlt;
    const float expWeq = __expf(swv - maxF);
    const float expLeq = __expf(minF - slv);
    const float invW = 1.0f / (sW + (float)eWc * expWeq);
    const float invL = 1.0f / (sL + (float)eLc * expLeq);
    const float wEq = expWeq * invW;
    const float lEq = expLeq * invL;

    float4* outL = reinterpret_cast<float4*>(out + (size_t)row * S);
    float4* outSh = reinterpret_cast<float4*>(out + (size_t)BATCH * S + (size_t)row * S);
    const bool noTie = (nWeq == eWc) && (nLeq == eLc);

    if (noTie) {
        // ---- write: one expf per element, branch-free selects ----
#pragma unroll
        for (int k = 0; k < 2; k++) {
            float lw[4], sw4[4];
#pragma unroll
            for (int c = 0; c < 4; c++) {
                float s = fr[k * 4 + c];
                bool gtW = (s > swv), ltL = (s < slv);
                float ex = __expf(gtW ? (s - maxF) : (minF - s));
                lw[c]  = gtW ? ex * invW : ((s == swv) ? wEq : 0.0f);
                sw4[c] = ltL ? ex * invL : ((s == slv) ? lEq : 0.0f);
            }
            outL[tid + k * NT]  = make_float4(lw[0], lw[1], lw[2], lw[3]);
            outSh[tid + k * NT] = make_float4(sw4[0], sw4[1], sw4[2], sw4[3]);
        }
    } else {
        // ---- RARE tie path: rank equals by global index (k, tid, c) via exscan ----
        uint32_t qW0 = 0, qW1 = 0, qL0 = 0, qL1 = 0;
#pragma unroll
        for (int c = 0; c < 4; c++) {
            qW0 += (fr[c] == swv);       qL0 += (fr[c] == slv);
            qW1 += (fr[4 + c] == swv);   qL1 += (fr[4 + c] == slv);
        }
        unsigned long long pk = (unsigned long long)qW0 | ((unsigned long long)qW1 << 16) |
                                ((unsigned long long)qL0 << 32) | ((unsigned long long)qL1 << 48);
        unsigned long long ex = block_exscan_u64(pk, st64);
        if (tid == NT - 1) sredu[7] = ex + pk;
        __syncthreads();
        unsigned long long tot = sredu[7];
        const uint32_t totW0 = (uint32_t)(tot & 0xFFFFull);
        const uint32_t totL0 = (uint32_t)((tot >> 32) & 0xFFFFull);
#pragma unroll
        for (int k = 0; k < 2; k++) {
            uint32_t beforeW = k ? totW0 + (uint32_t)((ex >> 16) & 0xFFFFull)
                                 : (uint32_t)(ex & 0xFFFFull);
            uint32_t beforeL = k ? totL0 + (uint32_t)((ex >> 48) & 0xFFFFull)
                                 : (uint32_t)((ex >> 32) & 0xFFFFull);
            float lw[4], sw4[4];
#pragma unroll
            for (int c = 0; c < 4; c++) {
                float s = fr[k * 4 + c];
                float lval = 0.0f, sval = 0.0f;
                if (s > swv) lval = __expf(s - maxF) * invW;
                else if (s == swv) { lval = (beforeW < (uint32_t)eWc) ? wEq : 0.0f; beforeW++; }
                if (s < slv) sval = __expf(minF - s) * invL;
                else if (s == slv) { sval = (beforeL < (uint32_t)eLc) ? lEq : 0.0f; beforeL++; }
                lw[c] = lval;
                sw4[c] = sval;
            }
            outL[tid + k * NT]  = make_float4(lw[0], lw[1], lw[2], lw[3]);
            outSh[tid + k * NT] = make_float4(sw4[0], sw4[1], sw4[2], sw4[3]);
        }
    }

    // ---- short_ratio passthrough (clipped) ----
    if (tid == 0) {
        float r = short_ratio[row];
        r = fminf(fmaxf(r, 0.0f), 1.0f);
        out[(size_t)2 * BATCH * S + row] = r;
    }
}

extern "C" void kernel_launch(void* const* d_in, const int* in_sizes, int n_in,
                              void* d_out, int out_size) {
    const float* scores = (const float*)d_in[0];
    const float* ratio  = (const float*)d_in[1];
    if (n_in >= 2 && in_sizes[0] == BATCH && in_sizes[1] == BATCH * S) {
        const float* t = scores; scores = ratio; ratio = t;
    }
    portfolio_kernel<<<BATCH, NT>>>(scores, ratio, (float*)d_out);
}

// round 11
// speedup vs baseline: 1.3596x; 1.3596x over previous
#include <cuda_runtime.h>
#include <cstdint>
#include <math_constants.h>

#define BATCH   16384
#define S       2048
#define G       256
#define NT      256
#define EPT     (S / NT)   // 8
#define LISTCAP 32
#define RANKW   1793u      // S-G+1 ascending
#define RANKL   256u       // G ascending
#define SHW     4.0f       // fixed softmax shift (winner side): exp(s - SHW)
#define SHL    -4.0f       // fixed softmax shift (loser side):  exp(SHL - s)

// ---- order-preserving float<->uint transforms (fallback path only) ----
__device__ __forceinline__ uint32_t f2u(float f) {
    uint32_t b = __float_as_uint(f);
    return b ^ ((b & 0x80000000u) ? 0xFFFFFFFFu : 0x80000000u);
}
__device__ __forceinline__ float u2f(uint32_t u) {
    uint32_t b = (u & 0x80000000u) ? (u ^ 0x80000000u) : ~u;
    return __uint_as_float(b);
}

// monotone value->bin map, 256 bins over [-4,4)
__device__ __forceinline__ int val2bin(float s) {
    int b = __float2int_rd(fmaf(s, 32.0f, 128.0f));
    return min(max(b, 0), 255);
}

// ---- block exclusive scan (u32), 256 threads ----
__device__ __forceinline__ uint32_t block_exscan_u32(uint32_t v, uint32_t* st) {
    const uint32_t full = 0xffffffffu;
    int lane = threadIdx.x & 31, w = threadIdx.x >> 5;
    uint32_t inc = v;
#pragma unroll
    for (int o = 1; o < 32; o <<= 1) {
        uint32_t t = __shfl_up_sync(full, inc, o);
        if (lane >= o) inc += t;
    }
    if (lane == 31) st[w] = inc;
    __syncthreads();
    if (threadIdx.x < 32) {
        uint32_t t = (lane < 8) ? st[lane] : 0u;
        uint32_t it = t;
#pragma unroll
        for (int o = 1; o < 8; o <<= 1) {
            uint32_t x = __shfl_up_sync(full, it, o);
            if (lane >= o) it += x;
        }
        if (lane < 8) st[lane] = it - t;
    }
    __syncthreads();
    uint32_t r = (inc - v) + st[w];
    __syncthreads();
    return r;
}

// ---- block exclusive scan (packed u64, independent 16-bit lanes) ----
__device__ __forceinline__ unsigned long long block_exscan_u64(unsigned long long v,
                                                               unsigned long long* st) {
    const uint32_t full = 0xffffffffu;
    int lane = threadIdx.x & 31, w = threadIdx.x >> 5;
    unsigned long long inc = v;
#pragma unroll
    for (int o = 1; o < 32; o <<= 1) {
        unsigned long long t = __shfl_up_sync(full, inc, o);
        if (lane >= o) inc += t;
    }
    if (lane == 31) st[w] = inc;
    __syncthreads();
    if (threadIdx.x < 32) {
        unsigned long long t = (lane < 8) ? st[lane] : 0ull;
        unsigned long long it = t;
#pragma unroll
        for (int o = 1; o < 8; o <<= 1) {
            unsigned long long x = __shfl_up_sync(full, it, o);
            if (lane >= o) it += x;
        }
        if (lane < 8) st[lane] = it - t;
    }
    __syncthreads();
    unsigned long long r = (inc - v) + st[w];
    __syncthreads();
    return r;
}

// ---- rare fallback: exact key radix select (11/11/10 bits), one rank ----
__device__ uint32_t radix_one_f(const float* fr, uint32_t rank,
                                uint32_t* hist, uint32_t* st, uint32_t* pub) {
    const int tid = threadIdx.x;
    uint32_t pfx = 0, r = rank;
#pragma unroll
    for (int rnd = 0; rnd < 3; rnd++) {
        reinterpret_cast<uint4*>(hist)[tid] = make_uint4(0, 0, 0, 0);
        reinterpret_cast<uint4*>(hist)[NT + tid] = make_uint4(0, 0, 0, 0);
        __syncthreads();
#pragma unroll
        for (int k = 0; k < EPT; k++) {
            uint32_t u = f2u(fr[k]);
            bool ok; uint32_t bin;
            if (rnd == 0)      { ok = true;                bin = u >> 21; }
            else if (rnd == 1) { ok = (u >> 21) == pfx;    bin = (u >> 10) & 0x7FFu; }
            else               { ok = (u >> 10) == pfx;    bin = u & 0x3FFu; }
            if (ok) atomicAdd(&hist[bin], 1u);
        }
        __syncthreads();
        const int nb = (rnd == 2) ? 4 : 8;
        uint32_t c[8], sum = 0;
#pragma unroll
        for (int k = 0; k < 8; k++) {
            c[k] = (k < nb) ? hist[tid * nb + k] : 0u;
            sum += c[k];
        }
        uint32_t exc = block_exscan_u32(sum, st);
        if (exc < r && r <= exc + sum) {
            uint32_t run = exc;
#pragma unroll
            for (int k = 0; k < 8; k++) {
                if (k < nb && r > run && r <= run + c[k]) {
                    pub[18] = tid * nb + k; pub[19] = r - run;
                }
                run += c[k];
            }
        }
        __syncthreads();
        uint32_t bin = pub[18]; r = pub[19];
        __syncthreads();
        pfx = (rnd == 2) ? ((pfx << 10) | bin) : ((pfx << 11) | bin);
    }
    return pfx;
}

__global__ __launch_bounds__(NT, 6)
void portfolio_kernel(const float* __restrict__ scores,
                      const float* __restrict__ short_ratio,
                      float* __restrict__ out) {
    const int row = blockIdx.x;
    const int tid = threadIdx.x;
    const int lane = tid & 31;
    const int wid = tid >> 5;
    const uint32_t full = 0xffffffffu;

    __shared__ __align__(16) uint32_t hist[2048];   // fast path: [0,256); fallback radix: all
    __shared__ uint32_t st32[8];
    __shared__ unsigned long long st64[8];
    __shared__ uint32_t pub[20];
    __shared__ uint32_t pub2[8];
    __shared__ uint32_t cnt2[2];
    __shared__ float listW[LISTCAP], listL[LISTCAP];
    __shared__ float sredf[16];
    __shared__ unsigned long long sredu[8];

    // ---- load row, clear histogram ----
    const float4* rowp = reinterpret_cast<const float4*>(scores + (size_t)row * S);
    float fr[8];
#pragma unroll
    for (int k = 0; k < 2; k++) {
        float4 v = rowp[tid + k * NT];
        fr[k * 4 + 0] = v.x; fr[k * 4 + 1] = v.y; fr[k * 4 + 2] = v.z; fr[k * 4 + 3] = v.w;
    }
    hist[tid] = 0;
    if (tid < 2) cnt2[tid] = 0;
    __syncthreads();

    // ---- histogram pass (256 value-domain bins) ----
#pragma unroll
    for (int k = 0; k < EPT; k++) atomicAdd(&hist[val2bin(fr[k])], 1u);
    __syncthreads();

    // ---- one scan (1 bin/thread) locates BOTH ranks + prefix counts ----
    {
        uint32_t sa = hist[tid];
        uint32_t ea = block_exscan_u32(sa, st32);
        if (ea < RANKW && RANKW <= ea + sa) {
            pub[0] = (uint32_t)tid; pub[1] = RANKW - ea; pub[2] = ea + sa;   // inclW
        }
        if (ea < RANKL && RANKL <= ea + sa) {
            pub[3] = (uint32_t)tid; pub[4] = RANKL - ea; pub[5] = ea;        // exclL
        }
        __syncthreads();
    }
    const int binW = (int)pub[0]; const uint32_t rW = pub[1]; const uint32_t inclW = pub[2];
    const int binL = (int)pub[3]; const uint32_t rL = pub[4]; const uint32_t exclL = pub[5];

    // ---- fused: capture candidates + coarse strict-bin exp-sums (branch-free exp) ----
    float sWc = 0.0f, sLc = 0.0f;
#pragma unroll
    for (int k = 0; k < EPT; k++) {
        float s = fr[k];
        int b = val2bin(s);
        if (b == binW) {
            uint32_t i = atomicAdd(&cnt2[0], 1u);
            if (i < LISTCAP) listW[i] = s;
        }
        if (b == binL) {
            uint32_t i = atomicAdd(&cnt2[1], 1u);
            if (i < LISTCAP) listL[i] = s;
        }
        bool gtB = (b > binW), ltB = (b < binL);
        float ex = __expf(gtB ? (s - SHW) : (SHL - s));
        sWc += gtB ? ex : 0.0f;
        sLc += ltB ? ex : 0.0f;
    }
#pragma unroll
    for (int o = 16; o; o >>= 1) {
        sWc += __shfl_xor_sync(full, sWc, o);
        sLc += __shfl_xor_sync(full, sLc, o);
    }
    if (lane == 0) { sredf[wid] = sWc; sredf[8 + wid] = sLc; }
    __syncthreads();
    const uint32_t cW = cnt2[0], cL = cnt2[1];
    const bool fastsel = (cW <= LISTCAP) && (cL <= LISTCAP);

    if (fastsel) {
        // ---- warps 0/1: sort candidates + ballots; warp 2: finalize coarse sums ----
        if (wid < 2) {
            const uint32_t n = (wid == 0) ? cW : cL;
            float v = ((uint32_t)lane < n) ? (wid == 0 ? listW[lane] : listL[lane])
                                           : CUDART_INF_F;
#pragma unroll
            for (int k = 2; k <= 32; k <<= 1) {
#pragma unroll
                for (int j = k >> 1; j > 0; j >>= 1) {
                    float o = __shfl_xor_sync(full, v, j);
                    bool up = ((lane & k) == 0);
                    bool lower = ((lane & j) == 0);
                    float mn = fminf(v, o), mx = fmaxf(v, o);
                    v = (lower == up) ? mn : mx;
                }
            }
            uint32_t rank = (wid == 0) ? rW : rL;   // 1-based ascending within bin
            float sel = __shfl_sync(full, v, (int)(rank - 1));
            bool valid = ((uint32_t)lane < n);
            if (wid == 0) {
                uint32_t mgt = __ballot_sync(full, valid && v > sel);
                uint32_t meq = __ballot_sync(full, valid && v == sel);
                float cs = (valid && v > sel) ? __expf(v - SHW) : 0.0f;
#pragma unroll
                for (int o = 16; o; o >>= 1) cs += __shfl_xor_sync(full, cs, o);
                if (lane == 0) {
                    pub2[0] = __float_as_uint(sel);
                    pub2[1] = __popc(mgt);
                    pub2[2] = __popc(meq);
                    pub2[3] = __float_as_uint(cs);
                }
            } else {
                uint32_t mlt = __ballot_sync(full, valid && v < sel);
                uint32_t meq = __ballot_sync(full, valid && v == sel);
                float cs = (valid && v < sel) ? __expf(SHL - v) : 0.0f;
#pragma unroll
                for (int o = 16; o; o >>= 1) cs += __shfl_xor_sync(full, cs, o);
                if (lane == 0) {
                    pub2[4] = __float_as_uint(sel);
                    pub2[5] = __popc(mlt);
                    pub2[6] = __popc(meq);
                    pub2[7] = __float_as_uint(cs);
                }
            }
        } else if (wid == 2) {
            float a = (lane < 8) ? sredf[lane] : 0.0f;
            float b = (lane < 8) ? sredf[8 + lane] : 0.0f;
#pragma unroll
            for (int o = 4; o; o >>= 1) {
                a += __shfl_xor_sync(full, a, o);
                b += __shfl_xor_sync(full, b, o);
            }
            if (lane == 0) { sredf[0] = a; sredf[8] = b; }
        }
        __syncthreads();
    }

    float swv, slv, sW, sL;
    int nWgt, nWeq, nLlt, nLeq;

    if (fastsel) {
        swv = __uint_as_float(pub2[0]);
        slv = __uint_as_float(pub2[4]);
        nWgt = (int)(S - inclW) + (int)pub2[1];
        nWeq = (int)pub2[2];
        sW = sredf[0] + __uint_as_float(pub2[3]);
        nLlt = (int)exclL + (int)pub2[5];
        nLeq = (int)pub2[6];
        sL = sredf[8] + __uint_as_float(pub2[7]);
    } else {
        // ---- RARE fallback: exact full-key radix select + full count pass ----
        uint32_t kW = radix_one_f(fr, RANKW, hist, st32, pub);
        uint32_t kL = radix_one_f(fr, RANKL, hist, st32, pub);
        swv = u2f(kW);
        slv = u2f(kL);
        unsigned long long packed = 0ull;
        float a2 = 0.0f, b2 = 0.0f;
#pragma unroll
        for (int k = 0; k < EPT; k++) {
            float s = fr[k];
            bool gtW = (s > swv), eqW = (s == swv), ltL = (s < slv), eqL = (s == slv);
            float ex = __expf(gtW ? (s - SHW) : (SHL - s));
            a2 += gtW ? ex : 0.0f;
            b2 += ltL ? ex : 0.0f;
            packed += (unsigned long long)gtW
                    + ((unsigned long long)eqW << 16)
                    + ((unsigned long long)ltL << 32)
                    + ((unsigned long long)eqL << 48);
        }
#pragma unroll
        for (int o = 16; o; o >>= 1) {
            packed += __shfl_xor_sync(full, packed, o);
            a2 += __shfl_xor_sync(full, a2, o);
            b2 += __shfl_xor_sync(full, b2, o);
        }
        if (lane == 0) { sredu[wid] = packed; sredf[wid] = a2; sredf[8 + wid] = b2; }
        __syncthreads();
        if (tid < 32) {
            unsigned long long c = (lane < 8) ? sredu[lane] : 0ull;
            float a = (lane < 8) ? sredf[lane] : 0.0f;
            float b = (lane < 8) ? sredf[8 + lane] : 0.0f;
#pragma unroll
            for (int o = 4; o; o >>= 1) {
                c += __shfl_xor_sync(full, c, o);
                a += __shfl_xor_sync(full, a, o);
                b += __shfl_xor_sync(full, b, o);
            }
            if (lane == 0) { sredu[0] = c; sredf[0] = a; sredf[8] = b; }
        }
        __syncthreads();
        packed = sredu[0];
        sW = sredf[0];
        sL = sredf[8];
        nWgt = (int)(packed & 0xFFFFu);
        nWeq = (int)((packed >> 16) & 0xFFFFu);
        nLlt = (int)((packed >> 32) & 0xFFFFu);
        nLeq = (int)((packed >> 48) & 0xFFFFu);
    }

    const int eWc = G - nWgt;
    const int eLc = G - nLlt;
    const float expWeq = __expf(swv - SHW);
    const float expLeq = __expf(SHL - slv);
    const float invW = 1.0f / (sW + (float)eWc * expWeq);
    const float invL = 1.0f / (sL + (float)eLc * expLeq);
    const float wEq = expWeq * invW;
    const float lEq = expLeq * invL;

    float4* outL = reinterpret_cast<float4*>(out + (size_t)row * S);
    float4* outSh = reinterpret_cast<float4*>(out + (size_t)BATCH * S + (size_t)row * S);
    const bool noTie = (nWeq == eWc) && (nLeq == eLc);

    if (noTie) {
        // ---- write: one expf per element, branch-free selects ----
#pragma unroll
        for (int k = 0; k < 2; k++) {
            float lw[4], sw4[4];
#pragma unroll
            for (int c = 0; c < 4; c++) {
                float s = fr[k * 4 + c];
                bool gtW = (s > swv), ltL = (s < slv);
                float ex = __expf(gtW ? (s - SHW) : (SHL - s));
                lw[c]  = gtW ? ex * invW : ((s == swv) ? wEq : 0.0f);
                sw4[c] = ltL ? ex * invL : ((s == slv) ? lEq : 0.0f);
            }
            outL[tid + k * NT]  = make_float4(lw[0], lw[1], lw[2], lw[3]);
            outSh[tid + k * NT] = make_float4(sw4[0], sw4[1], sw4[2], sw4[3]);
        }
    } else {
        // ---- RARE tie path: rank equals by global index (k, tid, c) via exscan ----
        uint32_t qW0 = 0, qW1 = 0, qL0 = 0, qL1 = 0;
#pragma unroll
        for (int c = 0; c < 4; c++) {
            qW0 += (fr[c] == swv);       qL0 += (fr[c] == slv);
            qW1 += (fr[4 + c] == swv);   qL1 += (fr[4 + c] == slv);
        }
        unsigned long long pk = (unsigned long long)qW0 | ((unsigned long long)qW1 << 16) |
                                ((unsigned long long)qL0 << 32) | ((unsigned long long)qL1 << 48);
        unsigned long long ex = block_exscan_u64(pk, st64);
        if (tid == NT - 1) sredu[7] = ex + pk;
        __syncthreads();
        unsigned long long tot = sredu[7];
        const uint32_t totW0 = (uint32_t)(tot & 0xFFFFull);
        const uint32_t totL0 = (uint32_t)((tot >> 32) & 0xFFFFull);
#pragma unroll
        for (int k = 0; k < 2; k++) {
            uint32_t beforeW = k ? totW0 + (uint32_t)((ex >> 16) & 0xFFFFull)
                                 : (uint32_t)(ex & 0xFFFFull);
            uint32_t beforeL = k ? totL0 + (uint32_t)((ex >> 48) & 0xFFFFull)
                                 : (uint32_t)((ex >> 32) & 0xFFFFull);
            float lw[4], sw4[4];
#pragma unroll
            for (int c = 0; c < 4; c++) {
                float s = fr[k * 4 + c];
                float lval = 0.0f, sval = 0.0f;
                if (s > swv) lval = __expf(s - SHW) * invW;
                else if (s == swv) { lval = (beforeW < (uint32_t)eWc) ? wEq : 0.0f; beforeW++; }
                if (s < slv) sval = __expf(SHL - s) * invL;
                else if (s == slv) { sval = (beforeL < (uint32_t)eLc) ? lEq : 0.0f; beforeL++; }
                lw[c] = lval;
                sw4[c] = sval;
            }
            outL[tid + k * NT]  = make_float4(lw[0], lw[1], lw[2], lw[3]);
            outSh[tid + k * NT] = make_float4(sw4[0], sw4[1], sw4[2], sw4[3]);
        }
    }

    // ---- short_ratio passthrough (clipped) ----
    if (tid == 0) {
        float r = short_ratio[row];
        r = fminf(fmaxf(r, 0.0f), 1.0f);
        out[(size_t)2 * BATCH * S + row] = r;
    }
}

extern "C" void kernel_launch(void* const* d_in, const int* in_sizes, int n_in,
                              void* d_out, int out_size) {
    const float* scores = (const float*)d_in[0];
    const float* ratio  = (const float*)d_in[1];
    if (n_in >= 2 && in_sizes[0] == BATCH && in_sizes[1] == BATCH * S) {
        const float* t = scores; scores = ratio; ratio = t;
    }
    portfolio_kernel<<<BATCH, NT>>>(scores, ratio, (float*)d_out);
}

// round 12
// speedup vs baseline: 1.4254x; 1.0484x over previous
#include <cuda_runtime.h>
#include <cstdint>
#include <math_constants.h>

#define BATCH   16384
#define S       2048
#define G       256
#define NT      256
#define EPT     (S / NT)   // 8
#define LISTCAP 32
#define RANKW   1793u      // S-G+1 ascending
#define RANKL   256u       // G ascending
#define SHW     4.0f       // fixed softmax shift (winner side): exp(s - SHW)
#define SHL    -4.0f       // fixed softmax shift (loser side):  exp(SHL - s)

// ---- order-preserving float<->uint transforms (fallback path only) ----
__device__ __forceinline__ uint32_t f2u(float f) {
    uint32_t b = __float_as_uint(f);
    return b ^ ((b & 0x80000000u) ? 0xFFFFFFFFu : 0x80000000u);
}
__device__ __forceinline__ float u2f(uint32_t u) {
    uint32_t b = (u & 0x80000000u) ? (u ^ 0x80000000u) : ~u;
    return __uint_as_float(b);
}

// monotone value->bin map, 256 bins over [-4,4)
__device__ __forceinline__ int val2bin(float s) {
    int b = __float2int_rd(fmaf(s, 32.0f, 128.0f));
    return min(max(b, 0), 255);
}

// ---- block exclusive scan (u32), 256 threads ----
__device__ __forceinline__ uint32_t block_exscan_u32(uint32_t v, uint32_t* st) {
    const uint32_t full = 0xffffffffu;
    int lane = threadIdx.x & 31, w = threadIdx.x >> 5;
    uint32_t inc = v;
#pragma unroll
    for (int o = 1; o < 32; o <<= 1) {
        uint32_t t = __shfl_up_sync(full, inc, o);
        if (lane >= o) inc += t;
    }
    if (lane == 31) st[w] = inc;
    __syncthreads();
    if (threadIdx.x < 32) {
        uint32_t t = (lane < 8) ? st[lane] : 0u;
        uint32_t it = t;
#pragma unroll
        for (int o = 1; o < 8; o <<= 1) {
            uint32_t x = __shfl_up_sync(full, it, o);
            if (lane >= o) it += x;
        }
        if (lane < 8) st[lane] = it - t;
    }
    __syncthreads();
    uint32_t r = (inc - v) + st[w];
    __syncthreads();
    return r;
}

// ---- block exclusive scan (packed u64; independent halves, no cross-carry) ----
__device__ __forceinline__ unsigned long long block_exscan_u64(unsigned long long v,
                                                               unsigned long long* st) {
    const uint32_t full = 0xffffffffu;
    int lane = threadIdx.x & 31, w = threadIdx.x >> 5;
    unsigned long long inc = v;
#pragma unroll
    for (int o = 1; o < 32; o <<= 1) {
        unsigned long long t = __shfl_up_sync(full, inc, o);
        if (lane >= o) inc += t;
    }
    if (lane == 31) st[w] = inc;
    __syncthreads();
    if (threadIdx.x < 32) {
        unsigned long long t = (lane < 8) ? st[lane] : 0ull;
        unsigned long long it = t;
#pragma unroll
        for (int o = 1; o < 8; o <<= 1) {
            unsigned long long x = __shfl_up_sync(full, it, o);
            if (lane >= o) it += x;
        }
        if (lane < 8) st[lane] = it - t;
    }
    __syncthreads();
    unsigned long long r = (inc - v) + st[w];
    __syncthreads();
    return r;
}

// ---- rare fallback: exact key radix select (11/11/10 bits), one rank ----
__device__ uint32_t radix_one_f(const float* fr, uint32_t rank,
                                uint32_t* hist, uint32_t* st, uint32_t* pub) {
    const int tid = threadIdx.x;
    uint32_t pfx = 0, r = rank;
#pragma unroll
    for (int rnd = 0; rnd < 3; rnd++) {
        reinterpret_cast<uint4*>(hist)[tid] = make_uint4(0, 0, 0, 0);
        reinterpret_cast<uint4*>(hist)[NT + tid] = make_uint4(0, 0, 0, 0);
        __syncthreads();
#pragma unroll
        for (int k = 0; k < EPT; k++) {
            uint32_t u = f2u(fr[k]);
            bool ok; uint32_t bin;
            if (rnd == 0)      { ok = true;                bin = u >> 21; }
            else if (rnd == 1) { ok = (u >> 21) == pfx;    bin = (u >> 10) & 0x7FFu; }
            else               { ok = (u >> 10) == pfx;    bin = u & 0x3FFu; }
            if (ok) atomicAdd(&hist[bin], 1u);
        }
        __syncthreads();
        const int nb = (rnd == 2) ? 4 : 8;
        uint32_t c[8], sum = 0;
#pragma unroll
        for (int k = 0; k < 8; k++) {
            c[k] = (k < nb) ? hist[tid * nb + k] : 0u;
            sum += c[k];
        }
        uint32_t exc = block_exscan_u32(sum, st);
        if (exc < r && r <= exc + sum) {
            uint32_t run = exc;
#pragma unroll
            for (int k = 0; k < 8; k++) {
                if (k < nb && r > run && r <= run + c[k]) {
                    pub[18] = tid * nb + k; pub[19] = r - run;
                }
                run += c[k];
            }
        }
        __syncthreads();
        uint32_t bin = pub[18]; r = pub[19];
        __syncthreads();
        pfx = (rnd == 2) ? ((pfx << 10) | bin) : ((pfx << 11) | bin);
    }
    return pfx;
}

// ---- fused capture + coarse strict-bin exp-sums (no syncs) ----
__device__ __forceinline__ void capture_sums(const float* fr, int binW, int binL,
                                             float* listW, float* listL,
                                             uint32_t* cntW, uint32_t* cntL,
                                             float& sWc, float& sLc) {
    sWc = 0.0f; sLc = 0.0f;
#pragma unroll
    for (int k = 0; k < EPT; k++) {
        float s = fr[k];
        int b = val2bin(s);
        if (b == binW) {
            uint32_t i = atomicAdd(cntW, 1u);
            if (i < LISTCAP) listW[i] = s;
        }
        if (b == binL) {
            uint32_t i = atomicAdd(cntL, 1u);
            if (i < LISTCAP) listL[i] = s;
        }
        bool gtB = (b > binW), ltB = (b < binL);
        float ex = __expf(gtB ? (s - SHW) : (SHL - s));
        sWc += gtB ? ex : 0.0f;
        sLc += ltB ? ex : 0.0f;
    }
}

// ---- fast write for one row (no syncs) ----
__device__ __forceinline__ void write_fast(const float* fr, float4* outL, float4* outSh,
                                           float swv, float slv, float invW, float invL,
                                           float wEq, float lEq, int tid) {
#pragma unroll
    for (int k = 0; k < 2; k++) {
        float lw[4], sw4[4];
#pragma unroll
        for (int c = 0; c < 4; c++) {
            float s = fr[k * 4 + c];
            bool gtW = (s > swv), ltL = (s < slv);
            float ex = __expf(gtW ? (s - SHW) : (SHL - s));
            lw[c]  = gtW ? ex * invW : ((s == swv) ? wEq : 0.0f);
            sw4[c] = ltL ? ex * invL : ((s == slv) ? lEq : 0.0f);
        }
        outL[tid + k * NT]  = make_float4(lw[0], lw[1], lw[2], lw[3]);
        outSh[tid + k * NT] = make_float4(sw4[0], sw4[1], sw4[2], sw4[3]);
    }
}

// ---- RARE tie path for one row (contains syncs; call block-uniformly) ----
__device__ void write_tie(const float* fr, float4* outL, float4* outSh,
                          float swv, float slv, float invW, float invL,
                          float wEq, float lEq, int eWc, int eLc,
                          unsigned long long* st64, unsigned long long* sredu, int tid) {
    uint32_t qW0 = 0, qW1 = 0, qL0 = 0, qL1 = 0;
#pragma unroll
    for (int c = 0; c < 4; c++) {
        qW0 += (fr[c] == swv);       qL0 += (fr[c] == slv);
        qW1 += (fr[4 + c] == swv);   qL1 += (fr[4 + c] == slv);
    }
    unsigned long long pk = (unsigned long long)qW0 | ((unsigned long long)qW1 << 16) |
                            ((unsigned long long)qL0 << 32) | ((unsigned long long)qL1 << 48);
    unsigned long long ex = block_exscan_u64(pk, st64);
    if (tid == NT - 1) sredu[7] = ex + pk;
    __syncthreads();
    unsigned long long tot = sredu[7];
    const uint32_t totW0 = (uint32_t)(tot & 0xFFFFull);
    const uint32_t totL0 = (uint32_t)((tot >> 32) & 0xFFFFull);
#pragma unroll
    for (int k = 0; k < 2; k++) {
        uint32_t beforeW = k ? totW0 + (uint32_t)((ex >> 16) & 0xFFFFull)
                             : (uint32_t)(ex & 0xFFFFull);
        uint32_t beforeL = k ? totL0 + (uint32_t)((ex >> 48) & 0xFFFFull)
                             : (uint32_t)((ex >> 32) & 0xFFFFull);
        float lw[4], sw4[4];
#pragma unroll
        for (int c = 0; c < 4; c++) {
            float s = fr[k * 4 + c];
            float lval = 0.0f, sval = 0.0f;
            if (s > swv) lval = __expf(s - SHW) * invW;
            else if (s == swv) { lval = (beforeW < (uint32_t)eWc) ? wEq : 0.0f; beforeW++; }
            if (s < slv) sval = __expf(SHL - s) * invL;
            else if (s == slv) { sval = (beforeL < (uint32_t)eLc) ? lEq : 0.0f; beforeL++; }
            lw[c] = lval;
            sw4[c] = sval;
        }
        outL[tid + k * NT]  = make_float4(lw[0], lw[1], lw[2], lw[3]);
        outSh[tid + k * NT] = make_float4(sw4[0], sw4[1], sw4[2], sw4[3]);
    }
    __syncthreads();   // protect st64/sredu for a possible second tie call
}

// ---- RARE fallback: exact params for one row (contains syncs; block-uniform) ----
__device__ void fallback_params(const float* fr, uint32_t* hist, uint32_t* st32,
                                uint32_t* pubF, unsigned long long* sredu, float* sredf,
                                int tid, int lane, int wid,
                                float& swv, float& slv, float& sW, float& sL,
                                int& nWgt, int& nWeq, int& nLlt, int& nLeq) {
    const uint32_t full = 0xffffffffu;
    uint32_t kW = radix_one_f(fr, RANKW, hist, st32, pubF);
    uint32_t kL = radix_one_f(fr, RANKL, hist, st32, pubF);
    swv = u2f(kW);
    slv = u2f(kL);
    unsigned long long packed = 0ull;
    float a2 = 0.0f, b2 = 0.0f;
#pragma unroll
    for (int k = 0; k < EPT; k++) {
        float s = fr[k];
        bool gtW = (s > swv), eqW = (s == swv), ltL = (s < slv), eqL = (s == slv);
        float ex = __expf(gtW ? (s - SHW) : (SHL - s));
        a2 += gtW ? ex : 0.0f;
        b2 += ltL ? ex : 0.0f;
        packed += (unsigned long long)gtW
                + ((unsigned long long)eqW << 16)
                + ((unsigned long long)ltL << 32)
                + ((unsigned long long)eqL << 48);
    }
#pragma unroll
    for (int o = 16; o; o >>= 1) {
        packed += __shfl_xor_sync(full, packed, o);
        a2 += __shfl_xor_sync(full, a2, o);
        b2 += __shfl_xor_sync(full, b2, o);
    }
    if (lane == 0) { sredu[wid] = packed; sredf[wid] = a2; sredf[8 + wid] = b2; }
    __syncthreads();
    if (tid < 32) {
        unsigned long long c = (lane < 8) ? sredu[lane] : 0ull;
        float a = (lane < 8) ? sredf[lane] : 0.0f;
        float b = (lane < 8) ? sredf[8 + lane] : 0.0f;
#pragma unroll
        for (int o = 4; o; o >>= 1) {
            c += __shfl_xor_sync(full, c, o);
            a += __shfl_xor_sync(full, a, o);
            b += __shfl_xor_sync(full, b, o);
        }
        if (lane == 0) { sredu[0] = c; sredf[0] = a; sredf[8] = b; }
    }
    __syncthreads();
    packed = sredu[0];
    sW = sredf[0];
    sL = sredf[8];
    nWgt = (int)(packed & 0xFFFFu);
    nWeq = (int)((packed >> 16) & 0xFFFFu);
    nLlt = (int)((packed >> 32) & 0xFFFFu);
    nLeq = (int)((packed >> 48) & 0xFFFFu);
    __syncthreads();   // protect scratch for subsequent calls
}

__global__ __launch_bounds__(NT, 5)
void portfolio_kernel(const float* __restrict__ scores,
                      const float* __restrict__ short_ratio,
                      float* __restrict__ out) {
    const int row0 = blockIdx.x * 2;
    const int tid = threadIdx.x;
    const int lane = tid & 31;
    const int wid = tid >> 5;
    const uint32_t full = 0xffffffffu;

    __shared__ __align__(16) uint32_t hist[2048];   // fast: [0,256)=row0, [256,512)=row1; fallback: all
    __shared__ uint32_t st32[8];
    __shared__ unsigned long long st64[8];
    __shared__ uint32_t pubA[6], pubB[6], pubF[20];
    __shared__ uint32_t pub2[16];
    __shared__ uint32_t cnt4[4];
    __shared__ float lists[4][LISTCAP];   // W0, L0, W1, L1
    __shared__ float sredf[32];
    __shared__ unsigned long long sredu[8];

    // ---- load both rows, clear histograms ----
    const float4* rp0 = reinterpret_cast<const float4*>(scores + (size_t)row0 * S);
    const float4* rp1 = reinterpret_cast<const float4*>(scores + (size_t)(row0 + 1) * S);
    float fr0[8], fr1[8];
#pragma unroll
    for (int k = 0; k < 2; k++) {
        float4 v = rp0[tid + k * NT];
        fr0[k * 4 + 0] = v.x; fr0[k * 4 + 1] = v.y; fr0[k * 4 + 2] = v.z; fr0[k * 4 + 3] = v.w;
        float4 w = rp1[tid + k * NT];
        fr1[k * 4 + 0] = w.x; fr1[k * 4 + 1] = w.y; fr1[k * 4 + 2] = w.z; fr1[k * 4 + 3] = w.w;
    }
    hist[tid] = 0;
    hist[NT + tid] = 0;
    if (tid < 4) cnt4[tid] = 0;
    __syncthreads();

    // ---- histogram pass, both rows ----
#pragma unroll
    for (int k = 0; k < EPT; k++) {
        atomicAdd(&hist[val2bin(fr0[k])], 1u);
        atomicAdd(&hist[NT + val2bin(fr1[k])], 1u);
    }
    __syncthreads();

    // ---- ONE packed scan locates both rows' ranks ----
    {
        uint32_t sa = hist[tid], sb = hist[NT + tid];
        unsigned long long e =
            block_exscan_u64((unsigned long long)sa | ((unsigned long long)sb << 32), st64);
        uint32_t ea = (uint32_t)e, eb = (uint32_t)(e >> 32);
        if (ea < RANKW && RANKW <= ea + sa) { pubA[0] = tid; pubA[1] = RANKW - ea; pubA[2] = ea + sa; }
        if (ea < RANKL && RANKL <= ea + sa) { pubA[3] = tid; pubA[4] = RANKL - ea; pubA[5] = ea; }
        if (eb < RANKW && RANKW <= eb + sb) { pubB[0] = tid; pubB[1] = RANKW - eb; pubB[2] = eb + sb; }
        if (eb < RANKL && RANKL <= eb + sb) { pubB[3] = tid; pubB[4] = RANKL - eb; pubB[5] = eb; }
        __syncthreads();
    }
    const int binW0 = (int)pubA[0], binL0 = (int)pubA[3];
    const uint32_t inclW0 = pubA[2], exclL0 = pubA[5];
    const int binW1 = (int)pubB[0], binL1 = (int)pubB[3];
    const uint32_t inclW1 = pubB[2], exclL1 = pubB[5];

    // ---- capture + coarse sums, both rows ----
    float sW0c, sL0c, sW1c, sL1c;
    capture_sums(fr0, binW0, binL0, lists[0], lists[1], &cnt4[0], &cnt4[1], sW0c, sL0c);
    capture_sums(fr1, binW1, binL1, lists[2], lists[3], &cnt4[2], &cnt4[3], sW1c, sL1c);
#pragma unroll
    for (int o = 16; o; o >>= 1) {
        sW0c += __shfl_xor_sync(full, sW0c, o);
        sL0c += __shfl_xor_sync(full, sL0c, o);
        sW1c += __shfl_xor_sync(full, sW1c, o);
        sL1c += __shfl_xor_sync(full, sL1c, o);
    }
    if (lane == 0) {
        sredf[wid] = sW0c; sredf[8 + wid] = sL0c;
        sredf[16 + wid] = sW1c; sredf[24 + wid] = sL1c;
    }
    __syncthreads();
    const bool fast0 = (cnt4[0] <= LISTCAP) && (cnt4[1] <= LISTCAP);
    const bool fast1 = (cnt4[2] <= LISTCAP) && (cnt4[3] <= LISTCAP);

    // ---- warps 0-3: sort W0/L0/W1/L1 + ballots; warps 4/5: finalize coarse sums ----
    if (wid < 4) {
        bool ok = (wid < 2) ? fast0 : fast1;
        if (ok) {
            const int side = wid & 1;   // 0 = winner side, 1 = loser side
            const uint32_t n = cnt4[wid];
            float v = ((uint32_t)lane < n) ? lists[wid][lane] : CUDART_INF_F;
#pragma unroll
            for (int k = 2; k <= 32; k <<= 1) {
#pragma unroll
                for (int j = k >> 1; j > 0; j >>= 1) {
                    float o = __shfl_xor_sync(full, v, j);
                    bool up = ((lane & k) == 0);
                    bool lower = ((lane & j) == 0);
                    float mn = fminf(v, o), mx = fmaxf(v, o);
                    v = (lower == up) ? mn : mx;
                }
            }
            uint32_t rank = (wid == 0) ? pubA[1] : (wid == 1) ? pubA[4]
                          : (wid == 2) ? pubB[1] : pubB[4];   // 1-based
            float sel = __shfl_sync(full, v, (int)(rank - 1));
            bool valid = ((uint32_t)lane < n);
            bool cmp = side ? (v < sel) : (v > sel);
            uint32_t mc = __ballot_sync(full, valid && cmp);
            uint32_t meq = __ballot_sync(full, valid && (v == sel));
            float cs = (valid && cmp) ? (side ? __expf(SHL - v) : __expf(v - SHW)) : 0.0f;
#pragma unroll
            for (int o = 16; o; o >>= 1) cs += __shfl_xor_sync(full, cs, o);
            if (lane == 0) {
                pub2[wid * 4 + 0] = __float_as_uint(sel);
                pub2[wid * 4 + 1] = __popc(mc);
                pub2[wid * 4 + 2] = __popc(meq);
                pub2[wid * 4 + 3] = __float_as_uint(cs);
            }
        }
    } else if (wid == 4) {
        float a = (lane < 8) ? sredf[lane] : 0.0f;
        float b = (lane < 8) ? sredf[8 + lane] : 0.0f;
#pragma unroll
        for (int o = 4; o; o >>= 1) {
            a += __shfl_xor_sync(full, a, o);
            b += __shfl_xor_sync(full, b, o);
        }
        if (lane == 0) { sredf[0] = a; sredf[8] = b; }
    } else if (wid == 5) {
        float a = (lane < 8) ? sredf[16 + lane] : 0.0f;
        float b = (lane < 8) ? sredf[24 + lane] : 0.0f;
#pragma unroll
        for (int o = 4; o; o >>= 1) {
            a += __shfl_xor_sync(full, a, o);
            b += __shfl_xor_sync(full, b, o);
        }
        if (lane == 0) { sredf[16] = a; sredf[24] = b; }
    }
    __syncthreads();

    // ---- read fast params for both rows into registers BEFORE any fallback ----
    float swv0 = __uint_as_float(pub2[0]);
    float slv0 = __uint_as_float(pub2[4]);
    int nWgt0 = (int)(S - inclW0) + (int)pub2[1];
    int nWeq0 = (int)pub2[2];
    float sW0 = sredf[0] + __uint_as_float(pub2[3]);
    int nLlt0 = (int)exclL0 + (int)pub2[5];
    int nLeq0 = (int)pub2[6];
    float sL0 = sredf[8] + __uint_as_float(pub2[7]);

    float swv1 = __uint_as_float(pub2[8]);
    float slv1 = __uint_as_float(pub2[12]);
    int nWgt1 = (int)(S - inclW1) + (int)pub2[9];
    int nWeq1 = (int)pub2[10];
    float sW1 = sredf[16] + __uint_as_float(pub2[11]);
    int nLlt1 = (int)exclL1 + (int)pub2[13];
    int nLeq1 = (int)pub2[14];
    float sL1 = sredf[24] + __uint_as_float(pub2[15]);
    __syncthreads();

    // ---- RARE fallbacks (block-uniform) ----
    if (!fast0) fallback_params(fr0, hist, st32, pubF, sredu, sredf, tid, lane, wid,
                                swv0, slv0, sW0, sL0, nWgt0, nWeq0, nLlt0, nLeq0);
    if (!fast1) fallback_params(fr1, hist, st32, pubF, sredu, sredf, tid, lane, wid,
                                swv1, slv1, sW1, sL1, nWgt1, nWeq1, nLlt1, nLeq1);

    // ---- row 0 epilogue ----
    {
        const int eWc = G - nWgt0, eLc = G - nLlt0;
        const float expWeq = __expf(swv0 - SHW);
        const float expLeq = __expf(SHL - slv0);
        const float invW = 1.0f / (sW0 + (float)eWc * expWeq);
        const float invL = 1.0f / (sL0 + (float)eLc * expLeq);
        const float wEq = expWeq * invW, lEq = expLeq * invL;
        float4* oL = reinterpret_cast<float4*>(out + (size_t)row0 * S);
        float4* oS = reinterpret_cast<float4*>(out + (size_t)BATCH * S + (size_t)row0 * S);
        if (nWeq0 == eWc && nLeq0 == eLc)
            write_fast(fr0, oL, oS, swv0, slv0, invW, invL, wEq, lEq, tid);
        else
            write_tie(fr0, oL, oS, swv0, slv0, invW, invL, wEq, lEq, eWc, eLc, st64, sredu, tid);
    }
    // ---- row 1 epilogue ----
    {
        const int eWc = G - nWgt1, eLc = G - nLlt1;
        const float expWeq = __expf(swv1 - SHW);
        const float expLeq = __expf(SHL - slv1);
        const float invW = 1.0f / (sW1 + (float)eWc * expWeq);
        const float invL = 1.0f / (sL1 + (float)eLc * expLeq);
        const float wEq = expWeq * invW, lEq = expLeq * invL;
        float4* oL = reinterpret_cast<float4*>(out + (size_t)(row0 + 1) * S);
        float4* oS = reinterpret_cast<float4*>(out + (size_t)BATCH * S + (size_t)(row0 + 1) * S);
        if (nWeq1 == eWc && nLeq1 == eLc)
            write_fast(fr1, oL, oS, swv1, slv1, invW, invL, wEq, lEq, tid);
        else
            write_tie(fr1, oL, oS, swv1, slv1, invW, invL, wEq, lEq, eWc, eLc, st64, sredu, tid);
    }

    // ---- short_ratio passthrough (clipped), both rows ----
    if (tid < 2) {
        float r = short_ratio[row0 + tid];
        r = fminf(fmaxf(r, 0.0f), 1.0f);
        out[(size_t)2 * BATCH * S + row0 + tid] = r;
    }
}

extern "C" void kernel_launch(void* const* d_in, const int* in_sizes, int n_in,
                              void* d_out, int out_size) {
    const float* scores = (const float*)d_in[0];
    const float* ratio  = (const float*)d_in[1];
    if (n_in >= 2 && in_sizes[0] == BATCH && in_sizes[1] == BATCH * S) {
        const float* t = scores; scores = ratio; ratio = t;
    }
    portfolio_kernel<<<BATCH / 2, NT>>>(scores, ratio, (float*)d_out);
}